// round 1
// baseline (speedup 1.0000x reference)
#include <cuda_runtime.h>
#include <math.h>

#define Hh 240
#define Ww 1216
#define Bb 4
#define HW (Hh*Ww)

// Scratch: tap tables (12B per pixel-tap) + ping-pong feat buffers.
__device__ unsigned g_pack[Bb*9*HW];   // y0 (int16 hi) | x0 (int16 lo), clamped to [-2, H/W]
__device__ unsigned g_wyx [Bb*9*HW];   // wy (unorm16 hi) | wx (unorm16 lo)
__device__ float    g_aff [Bb*9*HW];   // aff9 weight per tap
__device__ float    g_fa  [Bb*HW];
__device__ float    g_fb  [Bb*HW];

__device__ __forceinline__ float bilin_conf(const float* __restrict__ img, float sy, float sx)
{
    float fy = floorf(sy), fx = floorf(sx);
    float wy = sy - fy,  wx = sx - fx;
    int y0 = (int)fy, x0 = (int)fx;
    int y1 = y0 + 1, x1 = x0 + 1;
    float v00=0.f, v01=0.f, v10=0.f, v11=0.f;
    bool by0 = (unsigned)y0 < Hh, by1 = (unsigned)y1 < Hh;
    bool bx0 = (unsigned)x0 < Ww, bx1 = (unsigned)x1 < Ww;
    if (by0 && bx0) v00 = __ldg(img + y0*Ww + x0);
    if (by0 && bx1) v01 = __ldg(img + y0*Ww + x1);
    if (by1 && bx0) v10 = __ldg(img + y1*Ww + x0);
    if (by1 && bx1) v11 = __ldg(img + y1*Ww + x1);
    return (1.f-wy)*((1.f-wx)*v00 + wx*v01) + wy*((1.f-wx)*v10 + wx*v11);
}

// Post-processing for one pixel given its 24 conv outputs.
// acc[0..15]: offsets interleaved (y,x) per neighbor n: (acc[2n], acc[2n+1]).
// acc[16..23]: raw affinities.
__device__ __forceinline__ void post_pixel(const float acc[24], int b, int y, int xi,
    const float* __restrict__ cb, float asc,
    float* __restrict__ out_off, float* __restrict__ out_aff)
{
    int pi = y*Ww + xi;

    // offsets with zero center inserted at index 4 (9 neighbors)
    float offy[9], offx[9];
    #pragma unroll
    for (int m=0;m<9;m++){
        offy[m] = (m<4) ? acc[2*m]   : ((m==4) ? 0.f : acc[2*(m-1)]);
        offx[m] = (m<4) ? acc[2*m+1] : ((m==4) ? 0.f : acc[2*(m-1)+1]);
    }

    // affinities: tanh / (scale+1e-8), times bilinear-sampled confidence
    float a8[8], ssum = 0.f;
    #pragma unroll
    for (int k=0;k<8;k++){
        float av = tanhf(acc[16+k]) / asc;
        av *= bilin_conf(cb, (float)y + acc[2*k], (float)xi + acc[2*k+1]);
        a8[k] = av;
        ssum += fabsf(av);
    }
    float s = ssum + 1e-4f;
    if (s < 1.f) s = 1.f;
    float asum = 0.f;
    #pragma unroll
    for (int k=0;k<8;k++){ a8[k] = a8[k] / s; asum += a8[k]; }
    float aref = 1.f - asum;

    float affv[9];
    #pragma unroll
    for (int m=0;m<9;m++) affv[m] = (m<4) ? a8[m] : ((m==4) ? aref : a8[m-1]);

    // write off (18 ch) and aff9 (9 ch) outputs
    #pragma unroll
    for (int m=0;m<9;m++){
        out_off[((size_t)b*18 + 2*m    )*HW + pi] = offy[m];
        out_off[((size_t)b*18 + 2*m + 1)*HW + pi] = offx[m];
        out_aff[((size_t)b*9  + m      )*HW + pi] = affv[m];
    }

    // tap table for the 18 propagation iterations
    #pragma unroll
    for (int m=0;m<9;m++){
        float ty = (float)(y  + m/3 - 1) + offy[m];
        float tx = (float)(xi + m%3 - 1) + offx[m];
        float fy = floorf(ty), fx2 = floorf(tx);
        float wy = ty - fy, wx = tx - fx2;
        int y0 = (int)fy, x0 = (int)fx2;
        if (y0 < -2) y0 = -2;  if (y0 > Hh) y0 = Hh;   // clamp keeps invalidity
        if (x0 < -2) x0 = -2;  if (x0 > Ww) x0 = Ww;
        unsigned pk = ((unsigned)(y0 & 0xFFFF) << 16) | (unsigned)(x0 & 0xFFFF);
        unsigned uy = __float2uint_rn(wy * 65535.f);
        unsigned ux = __float2uint_rn(wx * 65535.f);
        int ti = (b*9 + m)*HW + pi;
        g_pack[ti] = pk;
        g_wyx [ti] = (uy << 16) | ux;
        g_aff [ti] = affv[m];
    }
}

// Fused: 3x3 conv (8ch -> 24ch) + all post-processing + initial blended feat.
// Each thread computes 2 adjacent-x pixels (shares conv weights & guidance window).
__global__ void __launch_bounds__(256) conv_post_kernel(
    const float* __restrict__ feat_init,
    const float* __restrict__ guidance,
    const float* __restrict__ confidence,
    const float* __restrict__ feat_fix,
    const float* __restrict__ w_oa,
    const float* __restrict__ b_oa,
    const float* __restrict__ ascale,
    float* __restrict__ out)
{
    __shared__ float wsh[1728];   // layout [c][dy][dx][o] for float4 o-reads
    for (int j = threadIdx.x; j < 1728; j += 256){
        int o = j % 24, r = j / 24;        // r = c*9 + dy*3 + dx
        wsh[j] = w_oa[o*72 + r];           // src: ((o*8+c)*3+dy)*3+dx = o*72 + r
    }
    __syncthreads();

    int t  = blockIdx.x*256 + threadIdx.x;
    int pp = t*2;                      // W even -> pair stays in one row
    int b  = pp / HW;
    int p  = pp - b*HW;
    int y  = p / Ww;
    int x  = p - y*Ww;                 // pixels (x, x+1)

    float acc0[24], acc1[24];
    #pragma unroll
    for (int o=0;o<24;o++){ float bo = __ldg(b_oa+o); acc0[o]=bo; acc1[o]=bo; }

    const float* gb = guidance + (size_t)b*8*HW;
    #pragma unroll 1
    for (int c=0;c<8;c++){
        #pragma unroll
        for (int dy=0;dy<3;dy++){
            int yy = y + dy - 1;
            if ((unsigned)yy >= Hh) continue;   // SAME zero padding
            const float* grow = gb + c*HW + yy*Ww;
            float gva[4];
            gva[0] = (x >= 1)     ? __ldg(grow + x - 1) : 0.f;
            gva[1] =                __ldg(grow + x);
            gva[2] =                __ldg(grow + x + 1);
            gva[3] = (x + 2 < Ww) ? __ldg(grow + x + 2) : 0.f;
            const float* wp = wsh + (c*9 + dy*3)*24;
            #pragma unroll
            for (int dx=0;dx<3;dx++){
                float a  = gva[dx];
                float b2 = gva[dx+1];
                const float4* w4p = (const float4*)(wp + dx*24);
                #pragma unroll
                for (int q=0;q<6;q++){
                    float4 w4 = w4p[q];
                    acc0[q*4+0] = fmaf(a,  w4.x, acc0[q*4+0]);
                    acc1[q*4+0] = fmaf(b2, w4.x, acc1[q*4+0]);
                    acc0[q*4+1] = fmaf(a,  w4.y, acc0[q*4+1]);
                    acc1[q*4+1] = fmaf(b2, w4.y, acc1[q*4+1]);
                    acc0[q*4+2] = fmaf(a,  w4.z, acc0[q*4+2]);
                    acc1[q*4+2] = fmaf(b2, w4.z, acc1[q*4+2]);
                    acc0[q*4+3] = fmaf(a,  w4.w, acc0[q*4+3]);
                    acc1[q*4+3] = fmaf(b2, w4.w, acc1[q*4+3]);
                }
            }
        }
    }

    const float* cb  = confidence + (size_t)b*HW;
    const float* fxb = feat_fix   + (size_t)b*HW;
    const float* fib = feat_init  + (size_t)b*HW;
    float asc = __ldg(ascale) + 1e-8f;

    float* out_off = out + (size_t)Bb*HW;       // after feat region
    float* out_aff = out + (size_t)Bb*HW*19;    // after feat + off regions

    post_pixel(acc0, b, y, x,   cb, asc, out_off, out_aff);
    post_pixel(acc1, b, y, x+1, cb, asc, out_off, out_aff);

    // pre-blended initial feat for iteration 0
    #pragma unroll
    for (int i=0;i<2;i++){
        int pi = p + i;
        float fv = __ldg(fxb + pi);
        g_fa[b*HW + pi] = (fv > 0.f) ? fv : __ldg(fib + pi);
    }
}

// One propagation iteration: 9-tap precomputed bilinear gather.
// Writes blended output for next iteration, or raw aggregate on the last.
__global__ void __launch_bounds__(256) prop_kernel(
    const float* __restrict__ feat_fix, float* __restrict__ dout, int it)
{
    int t = blockIdx.x*256 + threadIdx.x;   // grid sized exactly to Bb*HW
    int b = t / HW;
    int p = t - b*HW;

    const float* fin = (it & 1) ? g_fb : g_fa;
    const float* inb = fin + (size_t)b*HW;

    float acc = 0.f;
    #pragma unroll
    for (int k=0;k<9;k++){
        int ti = (b*9 + k)*HW + p;
        unsigned pk = g_pack[ti];
        unsigned wq = g_wyx [ti];
        float    av = g_aff [ti];
        int y0 = (int)(short)(pk >> 16);
        int x0 = (int)(short)(pk & 0xFFFFu);
        float wy = (float)(wq >> 16)      * (1.f/65535.f);
        float wx = (float)(wq & 0xFFFFu)  * (1.f/65535.f);
        int y1 = y0 + 1, x1 = x0 + 1;
        float v00=0.f, v01=0.f, v10=0.f, v11=0.f;
        bool by0 = (unsigned)y0 < Hh, by1 = (unsigned)y1 < Hh;
        bool bx0 = (unsigned)x0 < Ww, bx1 = (unsigned)x1 < Ww;
        const float* r0 = inb + y0*Ww;
        if (by0 && bx0) v00 = __ldg(r0 + x0);
        if (by0 && bx1) v01 = __ldg(r0 + x1);
        if (by1 && bx0) v10 = __ldg(r0 + Ww + x0);
        if (by1 && bx1) v11 = __ldg(r0 + Ww + x1);
        float v = (1.f-wy)*((1.f-wx)*v00 + wx*v01) + wy*((1.f-wx)*v10 + wx*v11);
        acc = fmaf(av, v, acc);
    }

    if (it != 17){
        float fv = __ldg(feat_fix + t);
        float* fout = (it & 1) ? g_fa : g_fb;
        fout[t] = (fv > 0.f) ? fv : acc;    // pre-blend for next iteration
    } else {
        dout[t] = acc;                      // final: raw aggregate
    }
}

extern "C" void kernel_launch(void* const* d_in, const int* in_sizes, int n_in,
                              void* d_out, int out_size)
{
    const float* feat_init  = (const float*)d_in[0];
    const float* guidance   = (const float*)d_in[1];
    const float* confidence = (const float*)d_in[2];
    const float* feat_fix   = (const float*)d_in[3];
    const float* w_oa       = (const float*)d_in[4];
    const float* b_oa       = (const float*)d_in[5];
    const float* ascale     = (const float*)d_in[6];
    float* out = (float*)d_out;

    (void)in_sizes; (void)n_in; (void)out_size;

    conv_post_kernel<<<(Bb*HW/2)/256, 256>>>(feat_init, guidance, confidence,
                                             feat_fix, w_oa, b_oa, ascale, out);
    for (int it = 0; it < 18; ++it)
        prop_kernel<<<(Bb*HW)/256, 256>>>(feat_fix, out, it);
}

// round 2
// speedup vs baseline: 1.1948x; 1.1948x over previous
#include <cuda_runtime.h>
#include <math.h>

#define Hh 240
#define Ww 1216
#define Bb 4
#define HW (Hh*Ww)
#define PH 244
#define PW 1220
#define PHW (PH*PW)

// Tap table: one u64 per (pixel, tap):
//   bits [0:19)  padded linear index (y0+2)*PW + (x0+2), y0 in [-2,Hh], x0 in [-2,Ww]
//   bits [19:31) wy unorm12 (x/4095)
//   bits [31:43) wx unorm12
//   bits [43:64) aff, signed fixed-point scale 2^-18 (|aff| <= 2)
__device__ unsigned long long g_tab[Bb*9*HW];
// Padded ping-pong feat buffers. Zero-initialized device globals; the 2-pixel
// border is NEVER written, so clamped out-of-range taps read exact zeros.
__device__ float g_fa[Bb*PHW];
__device__ float g_fb[Bb*PHW];

__device__ __forceinline__ unsigned long long pack2f(float a, float b){
    float2 t = make_float2(a, b);
    return *reinterpret_cast<unsigned long long*>(&t);
}
__device__ __forceinline__ float2 unpack2f(unsigned long long v){
    return *reinterpret_cast<float2*>(&v);
}

__device__ __forceinline__ float bilin_conf(const float* __restrict__ img, float sy, float sx)
{
    float fy = floorf(sy), fx = floorf(sx);
    float wy = sy - fy,  wx = sx - fx;
    int y0 = (int)fy, x0 = (int)fx;
    int y1 = y0 + 1, x1 = x0 + 1;
    float v00=0.f, v01=0.f, v10=0.f, v11=0.f;
    bool by0 = (unsigned)y0 < Hh, by1 = (unsigned)y1 < Hh;
    bool bx0 = (unsigned)x0 < Ww, bx1 = (unsigned)x1 < Ww;
    if (by0 && bx0) v00 = __ldg(img + y0*Ww + x0);
    if (by0 && bx1) v01 = __ldg(img + y0*Ww + x1);
    if (by1 && bx0) v10 = __ldg(img + y1*Ww + x0);
    if (by1 && bx1) v11 = __ldg(img + y1*Ww + x1);
    return (1.f-wy)*((1.f-wx)*v00 + wx*v01) + wy*((1.f-wx)*v10 + wx*v11);
}

// Post-processing for one pixel given its 24 conv outputs.
__device__ __forceinline__ void post_pixel(const float acc[24], int b, int y, int xi,
    const float* __restrict__ cb, float iasc,
    float* __restrict__ out_off, float* __restrict__ out_aff)
{
    int pi = y*Ww + xi;

    float offy[9], offx[9];
    #pragma unroll
    for (int m=0;m<9;m++){
        offy[m] = (m<4) ? acc[2*m]   : ((m==4) ? 0.f : acc[2*(m-1)]);
        offx[m] = (m<4) ? acc[2*m+1] : ((m==4) ? 0.f : acc[2*(m-1)+1]);
    }

    float a8[8], ssum = 0.f;
    #pragma unroll
    for (int k=0;k<8;k++){
        float av = tanhf(acc[16+k]) * iasc;
        av *= bilin_conf(cb, (float)y + acc[2*k], (float)xi + acc[2*k+1]);
        a8[k] = av;
        ssum += fabsf(av);
    }
    float s = ssum + 1e-4f;
    if (s < 1.f) s = 1.f;
    float inv = 1.0f / s;
    float asum = 0.f;
    #pragma unroll
    for (int k=0;k<8;k++){ a8[k] *= inv; asum += a8[k]; }
    float aref = 1.f - asum;

    float affv[9];
    #pragma unroll
    for (int m=0;m<9;m++) affv[m] = (m<4) ? a8[m] : ((m==4) ? aref : a8[m-1]);

    #pragma unroll
    for (int m=0;m<9;m++){
        out_off[((size_t)b*18 + 2*m    )*HW + pi] = offy[m];
        out_off[((size_t)b*18 + 2*m + 1)*HW + pi] = offx[m];
        out_aff[((size_t)b*9  + m      )*HW + pi] = affv[m];
    }

    // encode tap table
    #pragma unroll
    for (int m=0;m<9;m++){
        float ty = (float)(y  + m/3 - 1) + offy[m];
        float tx = (float)(xi + m%3 - 1) + offx[m];
        float fy = floorf(ty), fx2 = floorf(tx);
        float wy = ty - fy, wx = tx - fx2;
        int y0 = (int)fy, x0 = (int)fx2;
        if (y0 < -2) y0 = -2;  if (y0 > Hh) y0 = Hh;
        if (x0 < -2) x0 = -2;  if (x0 > Ww) x0 = Ww;
        unsigned idx = (unsigned)((y0+2)*PW + (x0+2));          // < 2^19
        unsigned uy = __float2uint_rn(wy * 4095.f);
        unsigned ux = __float2uint_rn(wx * 4095.f);
        int ia = __float2int_rn(affv[m] * 262144.f);            // |aff|<=2 -> fits 21-bit signed
        unsigned long long v =
              ((unsigned long long)((unsigned)ia & 0x1FFFFFu) << 43)
            | ((unsigned long long)ux << 31)
            | ((unsigned long long)uy << 19)
            | (unsigned long long)idx;
        g_tab[(b*9 + m)*HW + pi] = v;
    }
}

// Fused: 3x3 conv (8ch -> 24ch, f32x2 packed over a 2-pixel pair) + post + init feat.
__global__ void __launch_bounds__(256) conv_post_kernel(
    const float* __restrict__ feat_init,
    const float* __restrict__ guidance,
    const float* __restrict__ confidence,
    const float* __restrict__ feat_fix,
    const float* __restrict__ w_oa,
    const float* __restrict__ b_oa,
    const float* __restrict__ ascale,
    float* __restrict__ out)
{
    // duplicated weight pairs (w,w) for fma.rn.f32x2; layout [c][dy][dx][o]
    __shared__ unsigned long long wsh2[1728];
    for (int j = threadIdx.x; j < 1728; j += 256){
        int o = j % 24, r = j / 24;            // r = c*9 + dy*3 + dx
        float w = __ldg(w_oa + o*72 + r);      // src: o*72 + r
        wsh2[j] = pack2f(w, w);
    }
    __syncthreads();

    int t  = blockIdx.x*256 + threadIdx.x;
    int pp = t*2;                              // W even -> pair stays in one row
    int b  = pp / HW;
    int p  = pp - b*HW;
    int y  = p / Ww;
    int x  = p - y*Ww;                         // pixels (x, x+1)

    unsigned long long accp[24];
    #pragma unroll
    for (int o=0;o<24;o++){ float bo = __ldg(b_oa+o); accp[o] = pack2f(bo, bo); }

    const float* gb = guidance + (size_t)b*8*HW;
    #pragma unroll 1
    for (int c=0;c<8;c++){
        #pragma unroll
        for (int dy=0;dy<3;dy++){
            int yy = y + dy - 1;
            if ((unsigned)yy >= Hh) continue;   // SAME zero padding
            const float* grow = gb + c*HW + yy*Ww;
            float gva[4];
            gva[0] = (x >= 1)     ? __ldg(grow + x - 1) : 0.f;
            gva[1] =                __ldg(grow + x);
            gva[2] =                __ldg(grow + x + 1);
            gva[3] = (x + 2 < Ww) ? __ldg(grow + x + 2) : 0.f;
            #pragma unroll
            for (int dx=0;dx<3;dx++){
                unsigned long long ga = pack2f(gva[dx], gva[dx+1]);
                const ulonglong2* wp = (const ulonglong2*)(wsh2 + (c*9 + dy*3 + dx)*24);
                #pragma unroll
                for (int q=0;q<12;q++){
                    ulonglong2 w2 = wp[q];
                    asm("fma.rn.f32x2 %0, %1, %2, %0;" : "+l"(accp[2*q])   : "l"(ga), "l"(w2.x));
                    asm("fma.rn.f32x2 %0, %1, %2, %0;" : "+l"(accp[2*q+1]) : "l"(ga), "l"(w2.y));
                }
            }
        }
    }

    float acc0[24], acc1[24];
    #pragma unroll
    for (int o=0;o<24;o++){ float2 u = unpack2f(accp[o]); acc0[o]=u.x; acc1[o]=u.y; }

    const float* cb  = confidence + (size_t)b*HW;
    const float* fxb = feat_fix   + (size_t)b*HW;
    const float* fib = feat_init  + (size_t)b*HW;
    float iasc = 1.0f / (__ldg(ascale) + 1e-8f);

    float* out_off = out + (size_t)Bb*HW;
    float* out_aff = out + (size_t)Bb*HW*19;

    post_pixel(acc0, b, y, x,   cb, iasc, out_off, out_aff);
    post_pixel(acc1, b, y, x+1, cb, iasc, out_off, out_aff);

    // pre-blended initial feat into padded buffer interior
    #pragma unroll
    for (int i=0;i<2;i++){
        int pi = p + i;
        float fv = __ldg(fxb + pi);
        g_fa[b*PHW + (y+2)*PW + (x+i+2)] = (fv > 0.f) ? fv : __ldg(fib + pi);
    }
}

// One propagation iteration: 9 precomputed taps, unconditional 4-corner gather
// from the zero-bordered padded buffer.
__global__ void __launch_bounds__(256) prop_kernel(
    const float* __restrict__ feat_fix, float* __restrict__ dout, int it)
{
    int t = blockIdx.x*256 + threadIdx.x;   // grid sized exactly to Bb*HW
    int b = t / HW;
    int p = t - b*HW;
    int y = p / Ww;
    int x = p - y*Ww;

    const float* fin = ((it & 1) ? g_fb : g_fa) + (size_t)b*PHW;

    float acc = 0.f;
    #pragma unroll
    for (int k=0;k<9;k++){
        unsigned long long v = __ldg(&g_tab[(b*9 + k)*HW + p]);
        int idx  = (int)((unsigned)v & 0x7FFFFu);
        float wy = (float)((unsigned)(v >> 19) & 0xFFFu) * (1.f/4095.f);
        float wx = (float)((unsigned)(v >> 31) & 0xFFFu) * (1.f/4095.f);
        float af = (float)((long long)v >> 43) * (1.f/262144.f);
        const float* base = fin + idx;
        float v00 = __ldg(base);
        float v01 = __ldg(base + 1);
        float v10 = __ldg(base + PW);
        float v11 = __ldg(base + PW + 1);
        float top = v00 + wx*(v01 - v00);
        float bot = v10 + wx*(v11 - v10);
        acc = fmaf(af, top + wy*(bot - top), acc);
    }

    if (it != 17){
        float fv = __ldg(feat_fix + t);
        float* fout = ((it & 1) ? g_fa : g_fb) + (size_t)b*PHW;
        fout[(y+2)*PW + x + 2] = (fv > 0.f) ? fv : acc;   // pre-blend for next iter
    } else {
        dout[t] = acc;                                    // final: raw aggregate
    }
}

extern "C" void kernel_launch(void* const* d_in, const int* in_sizes, int n_in,
                              void* d_out, int out_size)
{
    const float* feat_init  = (const float*)d_in[0];
    const float* guidance   = (const float*)d_in[1];
    const float* confidence = (const float*)d_in[2];
    const float* feat_fix   = (const float*)d_in[3];
    const float* w_oa       = (const float*)d_in[4];
    const float* b_oa       = (const float*)d_in[5];
    const float* ascale     = (const float*)d_in[6];
    float* out = (float*)d_out;

    (void)in_sizes; (void)n_in; (void)out_size;

    conv_post_kernel<<<(Bb*HW/2)/256, 256>>>(feat_init, guidance, confidence,
                                             feat_fix, w_oa, b_oa, ascale, out);
    for (int it = 0; it < 18; ++it)
        prop_kernel<<<(Bb*HW)/256, 256>>>(feat_fix, out, it);
}